// round 5
// baseline (speedup 1.0000x reference)
#include <cuda_runtime.h>

#define SEQ   4096
#define CIN   7
#define NUMK  74
#define KH    8
#define KW    3
#define D     1536
#define HALFD 768
#define TLEN  (SEQ * KW)   // 12288
#define SPER  8            // s-rows per block
#define NH    (3 * SPER)   // 24 conv h-values per block

// ---------------- precomputed tables (device globals; no allocation) ----------------
// A[hi][i] = sincos(64*hi*div_i),  B[lo][i] = sincos(lo*div_i),  G[i] = sincos(div_i)
__device__ float g_A[64][HALFD][2];
__device__ float g_B[64][HALFD][2];
__device__ float g_G[HALFD][2];
// T2[a*7+b][f] = g(a)[f] + g(b)[f]   (temporal pair sums; indices are 0..6)
__device__ float g_T2[49][D];

__global__ void init_tables_kernel()
{
    int idx = blockIdx.x * blockDim.x + threadIdx.x;
    const float cexp = (float)(-9.210340371976184 / 1536.0); // -ln(10000)/d

    if (idx < 64 * HALFD) {
        int i = idx % HALFD;
        int r = idx / HALFD;
        float div = expf((2.0f * (float)i) * cexp);
        float sh, ch, sl, cl;
        sincosf((float)(64 * r) * div, &sh, &ch);
        g_A[r][i][0] = sh; g_A[r][i][1] = ch;
        sincosf((float)r * div, &sl, &cl);
        g_B[r][i][0] = sl; g_B[r][i][1] = cl;
        if (r == 1) { g_G[i][0] = sl; g_G[i][1] = cl; }  // sincos(1*div_i)
    }
    if (idx < 49 * HALFD) {
        int i = idx % HALFD;
        int p = idx / HALFD;
        int a = p / 7, b = p % 7;
        float div = expf((2.0f * (float)i) * cexp);
        float sa, ca, sb, cb;
        sincosf((float)a * div, &sa, &ca);
        sincosf((float)b * div, &sb, &cb);
        g_T2[p][2 * i]     = sa + sb;
        g_T2[p][2 * i + 1] = ca + cb;
    }
}

// dynamic smem layout (floats):
//   convS [NH][512]      : 12288 @ 0
//   wcsS  [KH][76]       : 608   @ 12288
//   sxS   [CIN][32]      : 224   @ 12896
//   t2iS  [SPER][2] int  : 16    @ 13120
#define SM_CONV   0
#define SM_WCS    12288
#define SM_SX     (SM_WCS + 608)
#define SM_T2I    (SM_SX + 224)
#define SMEM_BYTES ((SM_T2I + SPER * 2) * 4 + 64)

// ---------------- main kernel: 384 threads; thread owns one column f for 8 rows ----------------
__global__ __launch_bounds__(384, 3) void embed_kernel(
    const float* __restrict__ x,       // (4096, 7)
    const float* __restrict__ kern,    // (74, 8, 3)
    const int*   __restrict__ xm,      // (4096, 4)
    float*       __restrict__ out)     // (4096, 1536)
{
    extern __shared__ float smem[];
    float* __restrict__ convS = smem + SM_CONV;   // [NH][512], h-major
    float* __restrict__ wcsS  = smem + SM_WCS;    // [k][76]
    float* __restrict__ sxS   = smem + SM_SX;     // [c][32], 31 used
    int*   __restrict__ t2iS  = (int*)(smem + SM_T2I);

    const int s0  = blockIdx.x * SPER;   // aligned: hi = s>>6 constant; lo0+7 <= 63
    const int tid = threadIdx.x;

    // ---- stage weights: wc[o][k] = kern[o*24 + k*3 + 1]
    for (int e = tid; e < NUMK * KH; e += 384) {
        int o = e / KH, k = e - o * KH;
        wcsS[k * 76 + o] = kern[o * (KH * KW) + k * KW + 1];
    }
    // ---- stage x window: i in [0,31), t = 3*s0 - 4 + i
    if (tid < CIN * 31) {
        int c = tid / 31, i = tid - c * 31;
        int t = 3 * s0 - 4 + i;
        float v = 0.0f;
        if (t >= 0 && t < TLEN) {
            int row = t / 3 + t % 3;
            if (row > SEQ - 1) row = SEQ - 1;
            v = x[row * CIN + c];
        }
        sxS[c * 32 + i] = v;
    }
    // ---- stage temporal table indices
    if (tid < SPER) {
        int s = s0 + tid;
        int i0 = xm[s * 4 + 0], i1 = xm[s * 4 + 1],
            i2 = xm[s * 4 + 2], i3 = xm[s * 4 + 3];
        t2iS[2 * tid]     = i3 * 7 + i2;
        t2iS[2 * tid + 1] = i1 * 7 + i0;
    }
    __syncthreads();

    // =========== Phase 1: conv into smem, thread owns g-columns tid, tid+384 ==========
    for (int g = tid; g < 512; g += 384) {
        int c, o;
        if (g == 511) { c = 0; o = NUMK - 1; }
        else          { c = g / 73; o = g - c * 73; }

        float w[8];
#pragma unroll
        for (int k = 0; k < 8; k++) w[k] = wcsS[k * 76 + o];

        const float* __restrict__ sxc = sxS + c * 32;
        float v[8];
#pragma unroll
        for (int k = 0; k < 8; k++) v[k] = sxc[k];

#pragma unroll
        for (int h = 0; h < NH; h++) {
            float acc = 0.0f;
#pragma unroll
            for (int k = 0; k < 8; k++) acc += v[(h + k) & 7] * w[k];
            convS[h * 512 + g] = acc;
            if (h < NH - 1) v[h & 7] = sxc[h + 8];
        }
    }
    __syncthreads();

    // =========== Phase 2: one column per thread, 8 rows, pe rotated in registers ==========
    const int lane = tid & 127;          // 0..127
    const int jj   = tid >> 7;           // 0..2
    const int g0   = 4 * lane;
    const int f    = jj * 512 + g0;

    // seed pe(s0) from A (hi) and B (lo) rows  [layout: s,c,s,c]
    const float4 av = *(const float4*)(&g_A[s0 >> 6][0][0] + f);
    const float4 bv = *(const float4*)(&g_B[s0 & 63][0][0] + f);
    float4 pe;
    pe.x = av.x * bv.y + av.y * bv.x;    // sin
    pe.y = av.y * bv.y - av.x * bv.x;    // cos
    pe.z = av.z * bv.w + av.w * bv.z;
    pe.w = av.w * bv.w - av.z * bv.z;

    // rotation step table (6 KB, L1-resident)
    const float4 gv = *(const float4*)(&g_G[0][0] + f);

    // depth-1 prefetch of T2 rows
    float4 ta = *(const float4*)(g_T2[t2iS[0]] + f);
    float4 tb = *(const float4*)(g_T2[t2iS[1]] + f);

    float* __restrict__ outp = out + (size_t)s0 * D + f;
    const float* __restrict__ convp = convS + jj * 512 + g0;   // +3*512 per row

#pragma unroll
    for (int r = 0; r < SPER; r++) {
        const float4 cta = ta, ctb = tb;
        if (r < SPER - 1) {
            ta = *(const float4*)(g_T2[t2iS[2 * (r + 1)]] + f);
            tb = *(const float4*)(g_T2[t2iS[2 * (r + 1) + 1]] + f);
        }
        const float4 cv = *(const float4*)(convp);

        float4 res;
        res.x = cv.x + pe.x + cta.x + ctb.x;
        res.y = cv.y + pe.y + cta.y + ctb.y;
        res.z = cv.z + pe.z + cta.z + ctb.z;
        res.w = cv.w + pe.w + cta.w + ctb.w;
        *(float4*)outp = res;

        // rotate pe by div_f for next row
        float4 np;
        np.x = pe.x * gv.y + pe.y * gv.x;
        np.y = pe.y * gv.y - pe.x * gv.x;
        np.z = pe.z * gv.w + pe.w * gv.z;
        np.w = pe.w * gv.w - pe.z * gv.z;
        pe = np;

        outp  += D;
        convp += 3 * 512;
    }
}

// ---------------- launch ----------------
extern "C" void kernel_launch(void* const* d_in, const int* in_sizes, int n_in,
                              void* d_out, int out_size)
{
    const float* x     = nullptr;
    const float* kern  = nullptr;
    const int*   xmark = nullptr;
    for (int i = 0; i < n_in; i++) {
        if      (in_sizes[i] == SEQ * CIN)        x     = (const float*)d_in[i];
        else if (in_sizes[i] == NUMK * KH * KW)   kern  = (const float*)d_in[i];
        else if (in_sizes[i] == SEQ * 4)          xmark = (const int*)d_in[i];
    }

    cudaFuncSetAttribute(embed_kernel,
                         cudaFuncAttributeMaxDynamicSharedMemorySize, SMEM_BYTES);

    init_tables_kernel<<<(64 * HALFD + 255) / 256, 256>>>();
    embed_kernel<<<SEQ / SPER, 384, SMEM_BYTES>>>(x, kern, xmark, (float*)d_out);
}